// round 7
// baseline (speedup 1.0000x reference)
#include <cuda_runtime.h>
#include <cuda_bf16.h>
#include <cstdint>

#define DINLINE __device__ __forceinline__

// ---------------- problem sizes ----------------
#define B_  64
#define TN_ 131072
#define TE_ 262144
#define QD_ 768
#define PD_ 512
#define KD_ 512

// ---------------- device scratch ----------------
__device__ float g_qn[B_ * PD_];
__device__ float g_qe[B_ * PD_];
__device__ __nv_bfloat16 g_wtn[PD_ * KD_];   // W_n transposed [P][K], bf16
__device__ __nv_bfloat16 g_wte[PD_ * KD_];
__device__ float g_sn[TN_];
__device__ float g_se[TE_];

// ---------------- helpers ----------------
DINLINE void cp16(uint32_t s, const void* g) {
    asm volatile("cp.async.cg.shared.global [%0], [%1], 16;"
                 :: "r"(s), "l"(g) : "memory");
}
DINLINE void cp_commit() { asm volatile("cp.async.commit_group;" ::: "memory"); }
template<int N> DINLINE void cp_wait() {
    asm volatile("cp.async.wait_group %0;" :: "n"(N) : "memory");
}

DINLINE uint32_t smem_u32(const void* p) {
    uint32_t a;
    asm("{ .reg .u64 t; cvta.to.shared.u64 t, %1; cvt.u32.u64 %0, t; }"
        : "=r"(a) : "l"(p));
    return a;
}

DINLINE void mma_bf16(float* c, const uint32_t* a, const uint32_t* b) {
    asm volatile(
        "mma.sync.aligned.m16n8k16.row.col.f32.bf16.bf16.f32 "
        "{%0,%1,%2,%3}, {%4,%5,%6,%7}, {%8,%9}, {%0,%1,%2,%3};"
        : "+f"(c[0]), "+f"(c[1]), "+f"(c[2]), "+f"(c[3])
        : "r"(a[0]), "r"(a[1]), "r"(a[2]), "r"(a[3]),
          "r"(b[0]), "r"(b[1]));
}

DINLINE void ldm_x4(uint32_t& r0, uint32_t& r1, uint32_t& r2, uint32_t& r3,
                    uint32_t addr) {
    asm volatile("ldmatrix.sync.aligned.m8n8.x4.shared.b16 {%0,%1,%2,%3}, [%4];"
                 : "=r"(r0), "=r"(r1), "=r"(r2), "=r"(r3) : "r"(addr));
}

DINLINE uint32_t pack_bf16x2(float lo, float hi) {
    __nv_bfloat162 v = __float22bfloat162_rn(make_float2(lo, hi));
    return *reinterpret_cast<uint32_t*>(&v);
}

// ---------------- main fused GEMM ----------------
// CTA: 128 threads (4 warps, 2 wm x 2 wn, warp tile 64x64).
// Tile: M=128, N=128 (blockIdx.x in 0..3), K=512 in 16 chunks of 32.
// blockIdx.y in [0,3072): y<1024 -> nodes; else edges.
// 2 CTAs co-resident per SM (regs<=256, smem 51.7KB).
// SMEM (bf16, 80B padded rows):
//   A: 2 x (128 x 80B = 10240)  @ 0
//   B: 3 x (128 x 80B = 10240)  @ 20480
//   s_sm: 128 floats            @ 51200
#define ROWB   80u
#define ATILE  10240u
#define BTILE  10240u
#define BOFF   20480u
#define SM_OFF 51200u
#define SMEM_BYTES (51200 + 512)
#define NYN 1024             // node tiles in y

__global__ void __launch_bounds__(128, 2) k_main(
    const float* __restrict__ An, const float* __restrict__ Ae,
    const int* __restrict__ gidN, const int* __restrict__ gidE,
    const __nv_bfloat16* __restrict__ WtN, const __nv_bfloat16* __restrict__ WtE,
    const float* __restrict__ qN, const float* __restrict__ qE,
    const float* __restrict__ wvN, const float* __restrict__ wvE,
    float* __restrict__ sN, float* __restrict__ sE)
{
    extern __shared__ char smem[];
    float* s_sm = reinterpret_cast<float*>(smem + SM_OFF);

    const bool isNode = blockIdx.y < NYN;
    const int  ty     = isNode ? blockIdx.y : blockIdx.y - NYN;
    const float* __restrict__ A    = isNode ? An   : Ae;
    const int*   __restrict__ gid  = isNode ? gidN : gidE;
    const __nv_bfloat16* __restrict__ Wt = isNode ? WtN : WtE;
    const float* __restrict__ qeff = isNode ? qN   : qE;
    const float* __restrict__ wv   = isNode ? wvN  : wvE;
    float*       __restrict__ sOut = isNode ? sN   : sE;

    const int tid  = threadIdx.x;
    const int lane = tid & 31;
    const int warp = tid >> 5;
    const int wm   = warp & 1;   // M block of 64
    const int wn   = warp >> 1;  // N block of 64

    const int mBase = ty * 128;
    const int nBase = blockIdx.x * 128;

    const uint32_t sb = smem_u32(smem);

    if (tid < 128) s_sm[tid] = 0.f;

    // ---- A loader: 128 rows x 32 f32 per chunk; thread: 8 float4
    // rows (tid>>3) + i*16, quad (tid&7)
    const int aRow = tid >> 3;        // 0..15
    const int aQ   = tid & 7;         // 0..7
    const float* Abase = A + (size_t)(mBase + aRow) * KD_ + aQ * 4;

    float4 ra[8];
    auto ldA = [&](int kc) {
        const float* p = Abase + kc * 32;
#pragma unroll
        for (int i = 0; i < 8; ++i)
            ra[i] = *reinterpret_cast<const float4*>(p + (size_t)i * 16 * KD_);
    };
    auto stsA = [&](int buf) {
        const uint32_t base = sb + buf * ATILE + aRow * ROWB + aQ * 8;
#pragma unroll
        for (int i = 0; i < 8; ++i) {
            uint32_t lo = pack_bf16x2(ra[i].x, ra[i].y);
            uint32_t hi = pack_bf16x2(ra[i].z, ra[i].w);
            asm volatile("st.shared.v2.b32 [%0], {%1,%2};"
                         :: "r"(base + i * 16 * ROWB), "r"(lo), "r"(hi) : "memory");
        }
    };
    // B: 128 n-rows x 32 bf16 per chunk = 8KB = 512 x 16B; thread does 4 cp16
    // thread t covers n-row t, all 4 16B groups
    auto cpB = [&](int slot, int kc) {
        const uint32_t dst = sb + BOFF + slot * BTILE + tid * ROWB;
        const __nv_bfloat16* src = Wt + (size_t)(nBase + tid) * KD_ + kc * 32;
#pragma unroll
        for (int g = 0; g < 4; ++g)
            cp16(dst + g * 16, src + g * 8);
        cp_commit();
    };

    float c[4][8][4];
#pragma unroll
    for (int mt = 0; mt < 4; ++mt)
#pragma unroll
        for (int nt = 0; nt < 8; ++nt)
#pragma unroll
            for (int i = 0; i < 4; ++i) c[mt][nt][i] = 0.f;

    // ---- ldmatrix per-lane offsets ----
    const int j = lane >> 3;
    const uint32_t aLane = (uint32_t)(wm * 64 + ((j & 1) << 3) + (lane & 7)) * ROWB
                         + (uint32_t)(j >> 1) * 16u;
    const uint32_t bLane = (uint32_t)(wn * 64 + ((j >> 1) << 3) + (lane & 7)) * ROWB
                         + (uint32_t)(j & 1) * 16u;

    // ---- preamble ----
    ldA(0);
    cpB(0, 0);
    cpB(1, 1);
    stsA(0);
    ldA(1);
    cp_wait<1>();
    __syncthreads();

    auto mma_ks = [&](uint32_t aT2, uint32_t bT2, uint32_t ko) {
        uint32_t a[4][4];
#pragma unroll
        for (int mt = 0; mt < 4; ++mt)
            ldm_x4(a[mt][0], a[mt][1], a[mt][2], a[mt][3],
                   aT2 + mt * 16 * ROWB + ko);
        uint32_t b[8][2];
#pragma unroll
        for (int p = 0; p < 8; p += 2)
            ldm_x4(b[p][0], b[p][1], b[p + 1][0], b[p + 1][1],
                   bT2 + p * 8 * ROWB + ko);
#pragma unroll
        for (int mt = 0; mt < 4; ++mt)
#pragma unroll
            for (int nt = 0; nt < 8; ++nt)
                mma_bf16(c[mt][nt], a[mt], b[nt]);
    };

#pragma unroll 1
    for (int kc = 0; kc < 16; ++kc) {
        const int abuf = kc & 1;
        if (kc + 2 < 16) cpB((kc + 2) % 3, kc + 2);

        const uint32_t aT2 = sb + abuf * ATILE + aLane;
        const uint32_t bT2 = sb + BOFF + (kc % 3) * BTILE + bLane;

        mma_ks(aT2, bT2, 0);                 // ks = 0
        if (kc + 1 < 16) stsA(abuf ^ 1);     // STS next A chunk (overlaps MMA)
        if (kc + 2 < 16) ldA(kc + 2);        // LDG two chunks ahead
        mma_ks(aT2, bT2, 32);                // ks = 1

        if (kc + 2 < 16) cp_wait<1>(); else cp_wait<0>();
        __syncthreads();
    }

    // ---- epilogue: s[m] += sum_n tanh(D + qeff[gid[m]][n]) * wv[n] ----
    const int n0 = wn * 64 + 2 * (lane & 3);
#pragma unroll
    for (int mt = 0; mt < 4; ++mt) {
#pragma unroll
        for (int h = 0; h < 2; ++h) {
            const int row = wm * 64 + mt * 16 + (lane >> 2) + h * 8;
            const int g = __ldg(gid + mBase + row);
            const float* qrow = qeff + (size_t)g * PD_ + nBase;
            float s = 0.f;
#pragma unroll
            for (int nt = 0; nt < 8; ++nt) {
                const int nn = n0 + nt * 8;
                float2 q2 = *reinterpret_cast<const float2*>(qrow + nn);
                float2 w2 = *reinterpret_cast<const float2*>(wv + nBase + nn);
                float x0 = tanhf(c[mt][nt][h * 2 + 0] + q2.x);
                float x1 = tanhf(c[mt][nt][h * 2 + 1] + q2.y);
                s = fmaf(x0, w2.x, s);
                s = fmaf(x1, w2.y, s);
            }
            s += __shfl_xor_sync(0xffffffffu, s, 1);
            s += __shfl_xor_sync(0xffffffffu, s, 2);
            if ((lane & 3) == 0) atomicAdd(&s_sm[row], s);
        }
    }
    __syncthreads();
    if (tid < 128) atomicAdd(&sOut[mBase + tid], s_sm[tid]);
}

// ---------------- prep kernels ----------------
__global__ void k_zero(float* sn, float* se, float* qn, float* qe) {
    int i = blockIdx.x * blockDim.x + threadIdx.x;
    if (i < TN_) sn[i] = 0.f;
    if (i < TE_) se[i] = 0.f;
    if (i < B_ * PD_) { qn[i] = 0.f; qe[i] = 0.f; }
}

// Wt[p][k] = bf16(W[k][p])  (512x512), grid.z selects node/edge
__global__ void k_transpose(const float* __restrict__ Wn, const float* __restrict__ We,
                            __nv_bfloat16* __restrict__ WtN, __nv_bfloat16* __restrict__ WtE) {
    const float* W = blockIdx.z ? We : Wn;
    __nv_bfloat16* Wt = blockIdx.z ? WtE : WtN;
    __shared__ float tile[32][33];
    int x = blockIdx.x * 32 + threadIdx.x;   // p
    int y = blockIdx.y * 32 + threadIdx.y;   // k
#pragma unroll
    for (int j = 0; j < 32; j += 8)
        tile[threadIdx.y + j][threadIdx.x] = W[(y + j) * 512 + x];
    __syncthreads();
    int xo = blockIdx.y * 32 + threadIdx.x;  // k
    int yo = blockIdx.x * 32 + threadIdx.y;  // p
#pragma unroll
    for (int j = 0; j < 32; j += 8)
        Wt[(yo + j) * 512 + xo] = __float2bfloat16(tile[threadIdx.x][threadIdx.y + j]);
}

// split-k qproj, grid (B_, 8, 2): z selects node/edge weights.
__global__ void __launch_bounds__(256) k_qproj(
    const float* __restrict__ q,
    const float* __restrict__ WqN, const float* __restrict__ bqN, const float* __restrict__ bhN,
    const float* __restrict__ WqE, const float* __restrict__ bqE, const float* __restrict__ bhE,
    float* __restrict__ outN, float* __restrict__ outE) {
    const float* Wq = blockIdx.z ? WqE : WqN;
    const float* bq = blockIdx.z ? bqE : bqN;
    const float* bh = blockIdx.z ? bhE : bhN;
    float* out = blockIdx.z ? outE : outN;
    __shared__ float qs[96];
    const int b = blockIdx.x, ks = blockIdx.y;
    const int k0 = ks * 96;
    const int t = threadIdx.x;
    if (t < 96) qs[t] = q[b * QD_ + k0 + t];
    __syncthreads();
    const int p0 = t, p1 = t + 256;
    float a0 = 0.f, a1 = 0.f;
#pragma unroll 4
    for (int k = 0; k < 96; ++k) {
        const float* wrow = Wq + (size_t)(k0 + k) * 512;
        a0 = fmaf(qs[k], __ldg(wrow + p0), a0);
        a1 = fmaf(qs[k], __ldg(wrow + p1), a1);
    }
    if (ks == 0) {
        a0 += __ldg(bq + p0) + __ldg(bh + p0);
        a1 += __ldg(bq + p1) + __ldg(bh + p1);
    }
    atomicAdd(out + b * 512 + p0, a0);
    atomicAdd(out + b * 512 + p1, a1);
}

// ---------------- fused per-graph softmax (gid sorted -> contiguous segments) ----
__global__ void __launch_bounds__(256) k_soft(
    const float* __restrict__ sn, const float* __restrict__ se,
    const int* __restrict__ gidN, const int* __restrict__ gidE,
    float* __restrict__ out) {
    const bool isNode = blockIdx.x < 64;
    const int g = isNode ? blockIdx.x : blockIdx.x - 64;
    const float* s  = isNode ? sn : se;
    const int* gid  = isNode ? gidN : gidE;
    const int n     = isNode ? TN_ : TE_;
    float* o        = out + (isNode ? 0 : TN_);

    const int t = threadIdx.x;
    __shared__ float red[256];
    __shared__ int bounds[2];

    if (t < 2) {
        int target = g + t;
        int lo = 0, hi = n;
        while (lo < hi) {
            int mid = (lo + hi) >> 1;
            if (__ldg(gid + mid) < target) lo = mid + 1; else hi = mid;
        }
        bounds[t] = lo;
    }
    __syncthreads();
    const int lo = bounds[0], hi = bounds[1];

    float m = -3.0e38f;
    for (int i = lo + t; i < hi; i += 256) m = fmaxf(m, __ldg(s + i));
    red[t] = m;
    __syncthreads();
#pragma unroll
    for (int st = 128; st >= 1; st >>= 1) {
        if (t < st) red[t] = fmaxf(red[t], red[t + st]);
        __syncthreads();
    }
    m = red[0];
    __syncthreads();

    float z = 0.f;
    for (int i = lo + t; i < hi; i += 256) z += expf(__ldg(s + i) - m);
    red[t] = z;
    __syncthreads();
#pragma unroll
    for (int st = 128; st >= 1; st >>= 1) {
        if (t < st) red[t] += red[t + st];
        __syncthreads();
    }
    const float rz = 1.f / red[0];

    for (int i = lo + t; i < hi; i += 256)
        o[i] = expf(__ldg(s + i) - m) * rz;
}

// ---------------- launch ----------------
extern "C" void kernel_launch(void* const* d_in, const int* in_sizes, int n_in,
                              void* d_out, int out_size) {
    const float* question = (const float*)d_in[0];
    const float* nodes    = (const float*)d_in[1];
    const float* edges    = (const float*)d_in[2];
    const float* W_nq     = (const float*)d_in[3];
    const float* b_nq     = (const float*)d_in[4];
    const float* W_n      = (const float*)d_in[5];
    const float* b_n      = (const float*)d_in[6];
    const float* w_nv     = (const float*)d_in[7];
    // d_in[8] = b_nv — softmax shift-invariant, unused
    const float* W_eq     = (const float*)d_in[9];
    const float* b_eq     = (const float*)d_in[10];
    const float* W_e      = (const float*)d_in[11];
    const float* b_e      = (const float*)d_in[12];
    const float* w_ev     = (const float*)d_in[13];
    // d_in[14] = b_ev — unused
    const int* node_gid   = (const int*)d_in[15];
    const int* edge_gid   = (const int*)d_in[16];
    float* out = (float*)d_out;

    float *qn, *qe, *sn, *se;
    __nv_bfloat16 *wtn, *wte;
    cudaGetSymbolAddress((void**)&qn,  g_qn);
    cudaGetSymbolAddress((void**)&qe,  g_qe);
    cudaGetSymbolAddress((void**)&wtn, g_wtn);
    cudaGetSymbolAddress((void**)&wte, g_wte);
    cudaGetSymbolAddress((void**)&sn,  g_sn);
    cudaGetSymbolAddress((void**)&se,  g_se);

    cudaFuncSetAttribute(k_main, cudaFuncAttributeMaxDynamicSharedMemorySize, SMEM_BYTES);

    k_zero<<<TE_ / 512, 512>>>(sn, se, qn, qe);
    k_transpose<<<dim3(16, 16, 2), dim3(32, 8)>>>(W_n, W_e, wtn, wte);
    k_qproj<<<dim3(B_, 8, 2), 256>>>(question,
                                     W_nq, b_nq, b_n,
                                     W_eq, b_eq, b_e, qn, qe);

    k_main<<<dim3(4, NYN + TE_ / 128), 128, SMEM_BYTES>>>(
        nodes, edges, node_gid, edge_gid, wtn, wte, qn, qe, w_nv, w_ev, sn, se);

    k_soft<<<128, 256>>>(sn, se, node_gid, edge_gid, out);
}

// round 8
// speedup vs baseline: 1.0414x; 1.0414x over previous
#include <cuda_runtime.h>
#include <cuda_bf16.h>
#include <cstdint>

#define DINLINE __device__ __forceinline__

// ---------------- problem sizes ----------------
#define B_  64
#define TN_ 131072
#define TE_ 262144
#define QD_ 768
#define PD_ 512
#define KD_ 512

// ---------------- device scratch ----------------
__device__ float g_qn[B_ * PD_];
__device__ float g_qe[B_ * PD_];
__device__ __nv_bfloat16 g_wtn[PD_ * KD_];   // W_n transposed [P][K], bf16
__device__ __nv_bfloat16 g_wte[PD_ * KD_];
__device__ float g_sn[TN_];
__device__ float g_se[TE_];

// ---------------- helpers ----------------
DINLINE void cp16(uint32_t s, const void* g) {
    asm volatile("cp.async.cg.shared.global [%0], [%1], 16;"
                 :: "r"(s), "l"(g) : "memory");
}
DINLINE void cp_commit() { asm volatile("cp.async.commit_group;" ::: "memory"); }
template<int N> DINLINE void cp_wait() {
    asm volatile("cp.async.wait_group %0;" :: "n"(N) : "memory");
}

DINLINE uint32_t smem_u32(const void* p) {
    uint32_t a;
    asm("{ .reg .u64 t; cvta.to.shared.u64 t, %1; cvt.u32.u64 %0, t; }"
        : "=r"(a) : "l"(p));
    return a;
}

DINLINE void mma_bf16(float* c, const uint32_t* a, const uint32_t* b) {
    asm volatile(
        "mma.sync.aligned.m16n8k16.row.col.f32.bf16.bf16.f32 "
        "{%0,%1,%2,%3}, {%4,%5,%6,%7}, {%8,%9}, {%0,%1,%2,%3};"
        : "+f"(c[0]), "+f"(c[1]), "+f"(c[2]), "+f"(c[3])
        : "r"(a[0]), "r"(a[1]), "r"(a[2]), "r"(a[3]),
          "r"(b[0]), "r"(b[1]));
}

DINLINE void ldm_x4(uint32_t& r0, uint32_t& r1, uint32_t& r2, uint32_t& r3,
                    uint32_t addr) {
    asm volatile("ldmatrix.sync.aligned.m8n8.x4.shared.b16 {%0,%1,%2,%3}, [%4];"
                 : "=r"(r0), "=r"(r1), "=r"(r2), "=r"(r3) : "r"(addr));
}

DINLINE uint32_t pack_bf16x2(float lo, float hi) {
    __nv_bfloat162 v = __float22bfloat162_rn(make_float2(lo, hi));
    return *reinterpret_cast<uint32_t*>(&v);
}

// ---------------- main fused GEMM ----------------
// CTA: 256 threads (8 warps, 4 wm x 2 wn, warp tile 64x64).
// Tile: M=256, N=128 (blockIdx.x in 0..3), K=512 in 8 chunks of 64.
// blockIdx.y in [0,1536): y<512 -> nodes; else edges.
// SMEM (bf16, 144B padded rows: 64 bf16 = 128B + 16B pad, stride 9*16B
// coprime with 32 banks -> ldmatrix conflict-free):
//   A: 2 x (256 x 144B = 36864)  @ 0
//   B: 2 x (128 x 144B = 18432)  @ 73728
//   s_sm: 256 floats             @ 110592
#define ROWB   144u
#define ATILE  36864u
#define BTILE  18432u
#define BOFF   73728u
#define SM_OFF 110592u
#define SMEM_BYTES (110592 + 1024)
#define NYN 512              // node tiles in y

__global__ void __launch_bounds__(256, 1) k_main(
    const float* __restrict__ An, const float* __restrict__ Ae,
    const int* __restrict__ gidN, const int* __restrict__ gidE,
    const __nv_bfloat16* __restrict__ WtN, const __nv_bfloat16* __restrict__ WtE,
    const float* __restrict__ qN, const float* __restrict__ qE,
    const float* __restrict__ wvN, const float* __restrict__ wvE,
    float* __restrict__ sN, float* __restrict__ sE)
{
    extern __shared__ char smem[];
    float* s_sm = reinterpret_cast<float*>(smem + SM_OFF);

    const bool isNode = blockIdx.y < NYN;
    const int  ty     = isNode ? blockIdx.y : blockIdx.y - NYN;
    const float* __restrict__ A    = isNode ? An   : Ae;
    const int*   __restrict__ gid  = isNode ? gidN : gidE;
    const __nv_bfloat16* __restrict__ Wt = isNode ? WtN : WtE;
    const float* __restrict__ qeff = isNode ? qN   : qE;
    const float* __restrict__ wv   = isNode ? wvN  : wvE;
    float*       __restrict__ sOut = isNode ? sN   : sE;

    const int tid  = threadIdx.x;
    const int lane = tid & 31;
    const int warp = tid >> 5;
    const int wm   = warp & 3;   // M block of 64
    const int wn   = warp >> 2;  // N block of 64

    const int mBase = ty * 256;
    const int nBase = blockIdx.x * 128;

    const uint32_t sb = smem_u32(smem);

    s_sm[tid] = 0.f;

    // ---- A loader: 256 rows x 64 f32 per chunk, in two k-halves of 32.
    // Per half: thread does 8 float4 (rows (tid>>3)+i*32, quad tid&7).
    const int aRow = tid >> 3;
    const int aQ   = tid & 7;
    const float* Abase = A + (size_t)(mBase + aRow) * KD_ + aQ * 4;

    float4 ra[8];
    auto ldA = [&](int kc, int half) {
        const float* p = Abase + kc * 64 + half * 32;
#pragma unroll
        for (int i = 0; i < 8; ++i)
            ra[i] = *reinterpret_cast<const float4*>(p + (size_t)i * 32 * KD_);
    };
    auto stsA = [&](int buf, int half) {
        const uint32_t base = sb + buf * ATILE + aRow * ROWB + half * 64u + aQ * 8;
#pragma unroll
        for (int i = 0; i < 8; ++i) {
            uint32_t lo = pack_bf16x2(ra[i].x, ra[i].y);
            uint32_t hi = pack_bf16x2(ra[i].z, ra[i].w);
            asm volatile("st.shared.v2.b32 [%0], {%1,%2};"
                         :: "r"(base + i * 32 * ROWB), "r"(lo), "r"(hi) : "memory");
        }
    };
    // B: 128 n-rows x 64 bf16 per chunk = 16KB = 1024 x 16B; thread does 4 cp16
    const int bIdx0 = tid * 4;
    auto cpB = [&](int slot, int kc) {
#pragma unroll
        for (int j = 0; j < 4; ++j) {
            int idx = bIdx0 + j;
            int n = idx >> 3, g = idx & 7;
            cp16(sb + BOFF + slot * BTILE + n * ROWB + g * 16,
                 Wt + (size_t)(nBase + n) * KD_ + kc * 64 + g * 8);
        }
        cp_commit();
    };

    float c[4][8][4];
#pragma unroll
    for (int mt = 0; mt < 4; ++mt)
#pragma unroll
        for (int nt = 0; nt < 8; ++nt)
#pragma unroll
            for (int i = 0; i < 4; ++i) c[mt][nt][i] = 0.f;

    // ---- ldmatrix per-lane offsets ----
    const int j = lane >> 3;
    const uint32_t aLane = (uint32_t)(wm * 64 + ((j & 1) << 3) + (lane & 7)) * ROWB
                         + (uint32_t)(j >> 1) * 16u;
    const uint32_t bLane = (uint32_t)(wn * 64 + ((j >> 1) << 3) + (lane & 7)) * ROWB
                         + (uint32_t)(j & 1) * 16u;

    auto mma_ks = [&](uint32_t aT2, uint32_t bT2, uint32_t ko) {
        uint32_t a[4][4];
#pragma unroll
        for (int mt = 0; mt < 4; ++mt)
            ldm_x4(a[mt][0], a[mt][1], a[mt][2], a[mt][3],
                   aT2 + mt * 16 * ROWB + ko);
        uint32_t b[8][2];
#pragma unroll
        for (int p = 0; p < 8; p += 2)
            ldm_x4(b[p][0], b[p][1], b[p + 1][0], b[p + 1][1],
                   bT2 + p * 8 * ROWB + ko);
#pragma unroll
        for (int mt = 0; mt < 4; ++mt)
#pragma unroll
            for (int nt = 0; nt < 8; ++nt)
                mma_bf16(c[mt][nt], a[mt], b[nt]);
    };

    // ---- preamble: fill A buf0 (both halves), B slot0, prefetch A(1,h0)
    ldA(0, 0); stsA(0, 0);
    ldA(0, 1); stsA(0, 1);
    cpB(0, 0);
    ldA(1, 0);
    cp_wait<0>();
    __syncthreads();

#pragma unroll 1
    for (int kc = 0; kc < 8; ++kc) {
        const int abuf = kc & 1;
        if (kc + 1 < 8) cpB(abuf ^ 1, kc + 1);   // B prefetch 1 chunk ahead

        const uint32_t aT2 = sb + abuf * ATILE + aLane;
        const uint32_t bT2 = sb + BOFF + abuf * BTILE + bLane;

        mma_ks(aT2, bT2, 0);
        mma_ks(aT2, bT2, 32);
        if (kc + 1 < 8) { stsA(abuf ^ 1, 0); ldA(kc + 1, 1); }  // ra=(kc+1,h0)->STS; load h1
        mma_ks(aT2, bT2, 64);
        mma_ks(aT2, bT2, 96);
        if (kc + 1 < 8) { stsA(abuf ^ 1, 1); }                  // STS (kc+1,h1)
        if (kc + 2 < 8) { ldA(kc + 2, 0); }                     // prefetch (kc+2,h0)

        cp_wait<0>();
        __syncthreads();
    }

    // ---- epilogue: s[m] += sum_n tanh(D + qeff[gid[m]][n]) * wv[n] ----
    const int n0 = wn * 64 + 2 * (lane & 3);
#pragma unroll
    for (int mt = 0; mt < 4; ++mt) {
#pragma unroll
        for (int h = 0; h < 2; ++h) {
            const int row = wm * 64 + mt * 16 + (lane >> 2) + h * 8;
            const int g = __ldg(gid + mBase + row);
            const float* qrow = qeff + (size_t)g * PD_ + nBase;
            float s = 0.f;
#pragma unroll
            for (int nt = 0; nt < 8; ++nt) {
                const int nn = n0 + nt * 8;
                float2 q2 = *reinterpret_cast<const float2*>(qrow + nn);
                float2 w2 = *reinterpret_cast<const float2*>(wv + nBase + nn);
                float x0 = tanhf(c[mt][nt][h * 2 + 0] + q2.x);
                float x1 = tanhf(c[mt][nt][h * 2 + 1] + q2.y);
                s = fmaf(x0, w2.x, s);
                s = fmaf(x1, w2.y, s);
            }
            s += __shfl_xor_sync(0xffffffffu, s, 1);
            s += __shfl_xor_sync(0xffffffffu, s, 2);
            if ((lane & 3) == 0) atomicAdd(&s_sm[row], s);
        }
    }
    __syncthreads();
    atomicAdd(&sOut[mBase + tid], s_sm[tid]);
}

// ---------------- prep kernels ----------------
__global__ void k_zero(float* sn, float* se, float* qn, float* qe) {
    int i = blockIdx.x * blockDim.x + threadIdx.x;
    if (i < TN_) sn[i] = 0.f;
    if (i < TE_) se[i] = 0.f;
    if (i < B_ * PD_) { qn[i] = 0.f; qe[i] = 0.f; }
}

// Wt[p][k] = bf16(W[k][p])  (512x512), grid.z selects node/edge
__global__ void k_transpose(const float* __restrict__ Wn, const float* __restrict__ We,
                            __nv_bfloat16* __restrict__ WtN, __nv_bfloat16* __restrict__ WtE) {
    const float* W = blockIdx.z ? We : Wn;
    __nv_bfloat16* Wt = blockIdx.z ? WtE : WtN;
    __shared__ float tile[32][33];
    int x = blockIdx.x * 32 + threadIdx.x;   // p
    int y = blockIdx.y * 32 + threadIdx.y;   // k
#pragma unroll
    for (int j = 0; j < 32; j += 8)
        tile[threadIdx.y + j][threadIdx.x] = W[(y + j) * 512 + x];
    __syncthreads();
    int xo = blockIdx.y * 32 + threadIdx.x;  // k
    int yo = blockIdx.x * 32 + threadIdx.y;  // p
#pragma unroll
    for (int j = 0; j < 32; j += 8)
        Wt[(yo + j) * 512 + xo] = __float2bfloat16(tile[threadIdx.x][threadIdx.y + j]);
}

// split-k qproj, grid (B_, 8, 2): z selects node/edge weights.
__global__ void __launch_bounds__(256) k_qproj(
    const float* __restrict__ q,
    const float* __restrict__ WqN, const float* __restrict__ bqN, const float* __restrict__ bhN,
    const float* __restrict__ WqE, const float* __restrict__ bqE, const float* __restrict__ bhE,
    float* __restrict__ outN, float* __restrict__ outE) {
    const float* Wq = blockIdx.z ? WqE : WqN;
    const float* bq = blockIdx.z ? bqE : bqN;
    const float* bh = blockIdx.z ? bhE : bhN;
    float* out = blockIdx.z ? outE : outN;
    __shared__ float qs[96];
    const int b = blockIdx.x, ks = blockIdx.y;
    const int k0 = ks * 96;
    const int t = threadIdx.x;
    if (t < 96) qs[t] = q[b * QD_ + k0 + t];
    __syncthreads();
    const int p0 = t, p1 = t + 256;
    float a0 = 0.f, a1 = 0.f;
#pragma unroll 4
    for (int k = 0; k < 96; ++k) {
        const float* wrow = Wq + (size_t)(k0 + k) * 512;
        a0 = fmaf(qs[k], __ldg(wrow + p0), a0);
        a1 = fmaf(qs[k], __ldg(wrow + p1), a1);
    }
    if (ks == 0) {
        a0 += __ldg(bq + p0) + __ldg(bh + p0);
        a1 += __ldg(bq + p1) + __ldg(bh + p1);
    }
    atomicAdd(out + b * 512 + p0, a0);
    atomicAdd(out + b * 512 + p1, a1);
}

// ---------------- fused per-graph softmax (gid sorted -> contiguous segments) ----
__global__ void __launch_bounds__(256) k_soft(
    const float* __restrict__ sn, const float* __restrict__ se,
    const int* __restrict__ gidN, const int* __restrict__ gidE,
    float* __restrict__ out) {
    const bool isNode = blockIdx.x < 64;
    const int g = isNode ? blockIdx.x : blockIdx.x - 64;
    const float* s  = isNode ? sn : se;
    const int* gid  = isNode ? gidN : gidE;
    const int n     = isNode ? TN_ : TE_;
    float* o        = out + (isNode ? 0 : TN_);

    const int t = threadIdx.x;
    __shared__ float red[256];
    __shared__ int bounds[2];

    if (t < 2) {
        int target = g + t;
        int lo = 0, hi = n;
        while (lo < hi) {
            int mid = (lo + hi) >> 1;
            if (__ldg(gid + mid) < target) lo = mid + 1; else hi = mid;
        }
        bounds[t] = lo;
    }
    __syncthreads();
    const int lo = bounds[0], hi = bounds[1];

    float m = -3.0e38f;
    for (int i = lo + t; i < hi; i += 256) m = fmaxf(m, __ldg(s + i));
    red[t] = m;
    __syncthreads();
#pragma unroll
    for (int st = 128; st >= 1; st >>= 1) {
        if (t < st) red[t] = fmaxf(red[t], red[t + st]);
        __syncthreads();
    }
    m = red[0];
    __syncthreads();

    float z = 0.f;
    for (int i = lo + t; i < hi; i += 256) z += expf(__ldg(s + i) - m);
    red[t] = z;
    __syncthreads();
#pragma unroll
    for (int st = 128; st >= 1; st >>= 1) {
        if (t < st) red[t] += red[t + st];
        __syncthreads();
    }
    const float rz = 1.f / red[0];

    for (int i = lo + t; i < hi; i += 256)
        o[i] = expf(__ldg(s + i) - m) * rz;
}

// ---------------- launch ----------------
extern "C" void kernel_launch(void* const* d_in, const int* in_sizes, int n_in,
                              void* d_out, int out_size) {
    const float* question = (const float*)d_in[0];
    const float* nodes    = (const float*)d_in[1];
    const float* edges    = (const float*)d_in[2];
    const float* W_nq     = (const float*)d_in[3];
    const float* b_nq     = (const float*)d_in[4];
    const float* W_n      = (const float*)d_in[5];
    const float* b_n      = (const float*)d_in[6];
    const float* w_nv     = (const float*)d_in[7];
    // d_in[8] = b_nv — softmax shift-invariant, unused
    const float* W_eq     = (const float*)d_in[9];
    const float* b_eq     = (const float*)d_in[10];
    const float* W_e      = (const float*)d_in[11];
    const float* b_e      = (const float*)d_in[12];
    const float* w_ev     = (const float*)d_in[13];
    // d_in[14] = b_ev — unused
    const int* node_gid   = (const int*)d_in[15];
    const int* edge_gid   = (const int*)d_in[16];
    float* out = (float*)d_out;

    float *qn, *qe, *sn, *se;
    __nv_bfloat16 *wtn, *wte;
    cudaGetSymbolAddress((void**)&qn,  g_qn);
    cudaGetSymbolAddress((void**)&qe,  g_qe);
    cudaGetSymbolAddress((void**)&wtn, g_wtn);
    cudaGetSymbolAddress((void**)&wte, g_wte);
    cudaGetSymbolAddress((void**)&sn,  g_sn);
    cudaGetSymbolAddress((void**)&se,  g_se);

    cudaFuncSetAttribute(k_main, cudaFuncAttributeMaxDynamicSharedMemorySize, SMEM_BYTES);

    k_zero<<<TE_ / 512, 512>>>(sn, se, qn, qe);
    k_transpose<<<dim3(16, 16, 2), dim3(32, 8)>>>(W_n, W_e, wtn, wte);
    k_qproj<<<dim3(B_, 8, 2), 256>>>(question,
                                     W_nq, b_nq, b_n,
                                     W_eq, b_eq, b_e, qn, qe);

    k_main<<<dim3(4, NYN + TE_ / 256), 256, SMEM_BYTES>>>(
        nodes, edges, node_gid, edge_gid, wtn, wte, qn, qe, w_nv, w_ev, sn, se);

    k_soft<<<128, 256>>>(sn, se, node_gid, edge_gid, out);
}

// round 9
// speedup vs baseline: 1.0775x; 1.0346x over previous
#include <cuda_runtime.h>
#include <cuda_bf16.h>
#include <cstdint>

#define DINLINE __device__ __forceinline__

// ---------------- problem sizes ----------------
#define B_  64
#define TN_ 131072
#define TE_ 262144
#define QD_ 768
#define PD_ 512
#define KD_ 512

// ---------------- device scratch ----------------
__device__ float g_qn[B_ * PD_];
__device__ float g_qe[B_ * PD_];
__device__ __nv_bfloat16 g_wtn[PD_ * KD_];   // W_n transposed [P][K], bf16
__device__ __nv_bfloat16 g_wte[PD_ * KD_];
__device__ float g_sn[TN_];
__device__ float g_se[TE_];

// ---------------- helpers ----------------
DINLINE void cp16(uint32_t s, const void* g) {
    asm volatile("cp.async.cg.shared.global [%0], [%1], 16;"
                 :: "r"(s), "l"(g) : "memory");
}
DINLINE void cp_commit() { asm volatile("cp.async.commit_group;" ::: "memory"); }
template<int N> DINLINE void cp_wait() {
    asm volatile("cp.async.wait_group %0;" :: "n"(N) : "memory");
}

DINLINE uint32_t smem_u32(const void* p) {
    uint32_t a;
    asm("{ .reg .u64 t; cvta.to.shared.u64 t, %1; cvt.u32.u64 %0, t; }"
        : "=r"(a) : "l"(p));
    return a;
}

DINLINE void mma_bf16(float* c, const uint32_t* a, const uint32_t* b) {
    asm volatile(
        "mma.sync.aligned.m16n8k16.row.col.f32.bf16.bf16.f32 "
        "{%0,%1,%2,%3}, {%4,%5,%6,%7}, {%8,%9}, {%0,%1,%2,%3};"
        : "+f"(c[0]), "+f"(c[1]), "+f"(c[2]), "+f"(c[3])
        : "r"(a[0]), "r"(a[1]), "r"(a[2]), "r"(a[3]),
          "r"(b[0]), "r"(b[1]));
}

DINLINE void ldm_x4(uint32_t& r0, uint32_t& r1, uint32_t& r2, uint32_t& r3,
                    uint32_t addr) {
    asm volatile("ldmatrix.sync.aligned.m8n8.x4.shared.b16 {%0,%1,%2,%3}, [%4];"
                 : "=r"(r0), "=r"(r1), "=r"(r2), "=r"(r3) : "r"(addr));
}

DINLINE uint32_t pack_bf16x2(float lo, float hi) {
    __nv_bfloat162 v = __float22bfloat162_rn(make_float2(lo, hi));
    return *reinterpret_cast<uint32_t*>(&v);
}

// ---------------- main fused GEMM ----------------
// CTA: 256 threads (8 warps, 4 wm x 2 wn, warp tile 64x64).
// Tile: M=256, N=128 (blockIdx.x in 0..3), K=512 in 16 chunks of 32.
// blockIdx.y in [0,1536): y<512 -> nodes; else edges.
// SMEM (bf16, 80B padded rows):
//   A: 2 x (256 x 80B = 20480)  @ 0
//   B: 3 x (128 x 80B = 10240)  @ 40960
//   s_sm: 256 floats            @ 71680
#define ROWB   80u
#define ATILE  20480u
#define BTILE  10240u
#define BOFF   40960u
#define SM_OFF 71680u
#define SMEM_BYTES (71680 + 1024)
#define NYN 512              // node tiles in y

__global__ void __launch_bounds__(256, 1) k_main(
    const float* __restrict__ An, const float* __restrict__ Ae,
    const int* __restrict__ gidN, const int* __restrict__ gidE,
    const __nv_bfloat16* __restrict__ WtN, const __nv_bfloat16* __restrict__ WtE,
    const float* __restrict__ qN, const float* __restrict__ qE,
    const float* __restrict__ wvN, const float* __restrict__ wvE,
    float* __restrict__ sN, float* __restrict__ sE)
{
    extern __shared__ char smem[];
    float* s_sm = reinterpret_cast<float*>(smem + SM_OFF);

    const bool isNode = blockIdx.y < NYN;
    const int  ty     = isNode ? blockIdx.y : blockIdx.y - NYN;
    const float* __restrict__ A    = isNode ? An   : Ae;
    const int*   __restrict__ gid  = isNode ? gidN : gidE;
    const __nv_bfloat16* __restrict__ Wt = isNode ? WtN : WtE;
    const float* __restrict__ qeff = isNode ? qN   : qE;
    const float* __restrict__ wv   = isNode ? wvN  : wvE;
    float*       __restrict__ sOut = isNode ? sN   : sE;

    const int tid  = threadIdx.x;
    const int lane = tid & 31;
    const int warp = tid >> 5;
    const int wm   = warp & 3;   // M block of 64
    const int wn   = warp >> 2;  // N block of 64

    const int mBase = ty * 256;
    const int nBase = blockIdx.x * 128;

    const uint32_t sb = smem_u32(smem);

    s_sm[tid] = 0.f;

    // ---- A loader: 256 rows x 32 f32 per chunk; thread: 8 float4
    const int aRow = tid >> 3;
    const int aQ   = tid & 7;
    const float* Abase = A + (size_t)(mBase + aRow) * KD_ + aQ * 4;

    float4 ra[8];
    auto ldA = [&](int kc) {
        const float* p = Abase + kc * 32;
#pragma unroll
        for (int i = 0; i < 8; ++i)
            ra[i] = *reinterpret_cast<const float4*>(p + (size_t)i * 32 * KD_);
    };
    auto stsA = [&](int buf) {
        const uint32_t base = sb + buf * ATILE + aRow * ROWB + aQ * 8;
#pragma unroll
        for (int i = 0; i < 8; ++i) {
            uint32_t lo = pack_bf16x2(ra[i].x, ra[i].y);
            uint32_t hi = pack_bf16x2(ra[i].z, ra[i].w);
            asm volatile("st.shared.v2.b32 [%0], {%1,%2};"
                         :: "r"(base + i * 32 * ROWB), "r"(lo), "r"(hi) : "memory");
        }
    };
    // B: 128 n-rows x 32 bf16 per chunk = 8KB = 512 x 16B; thread does 2 cp16
    const int bIdx0 = tid * 2;
    auto cpB = [&](int slot, int kc) {
#pragma unroll
        for (int j = 0; j < 2; ++j) {
            int idx = bIdx0 + j;
            int n = idx >> 2, g = idx & 3;
            cp16(sb + BOFF + slot * BTILE + n * ROWB + g * 16,
                 Wt + (size_t)(nBase + n) * KD_ + kc * 32 + g * 8);
        }
        cp_commit();
    };

    float c[4][8][4];
#pragma unroll
    for (int mt = 0; mt < 4; ++mt)
#pragma unroll
        for (int nt = 0; nt < 8; ++nt)
#pragma unroll
            for (int i = 0; i < 4; ++i) c[mt][nt][i] = 0.f;

    // ---- ldmatrix per-lane offsets ----
    const int j = lane >> 3;
    const uint32_t aLane = (uint32_t)(wm * 64 + ((j & 1) << 3) + (lane & 7)) * ROWB
                         + (uint32_t)(j >> 1) * 16u;
    const uint32_t bLane = (uint32_t)(wn * 64 + ((j >> 1) << 3) + (lane & 7)) * ROWB
                         + (uint32_t)(j & 1) * 16u;

    // ---- register-resident A fragment sets (ping-pong, no copies) ----
    uint32_t aF0[4][4], aF1[4][4];

    auto ldA_frags = [&](uint32_t aT2, uint32_t ko, uint32_t (&a)[4][4]) {
#pragma unroll
        for (int mt = 0; mt < 4; ++mt)
            ldm_x4(a[mt][0], a[mt][1], a[mt][2], a[mt][3],
                   aT2 + mt * 16 * ROWB + ko);
    };

    // One MMA phase over 8 nt, B loaded in pairs and pipelined; optionally
    // preloads the next phase's A fragments under the last MMA group.
    auto phase = [&](const uint32_t (&aIn)[4][4], uint32_t (&aOut)[4][4],
                     uint32_t bT2, uint32_t ko,
                     uint32_t aT2n, uint32_t kon, bool preloadA) {
        uint32_t b[2][2][2];   // [buf][nt-in-pair][frag]
        ldm_x4(b[0][0][0], b[0][0][1], b[0][1][0], b[0][1][1], bT2 + ko);
#pragma unroll
        for (int p = 0; p < 4; ++p) {
            const int cb = p & 1, nb = cb ^ 1;
            if (p < 3) {
                ldm_x4(b[nb][0][0], b[nb][0][1], b[nb][1][0], b[nb][1][1],
                       bT2 + (uint32_t)(p + 1) * 16 * ROWB + ko);
            } else if (preloadA) {
                ldA_frags(aT2n, kon, aOut);
            }
#pragma unroll
            for (int mt = 0; mt < 4; ++mt) {
                mma_bf16(c[mt][2 * p],     aIn[mt], b[cb][0]);
                mma_bf16(c[mt][2 * p + 1], aIn[mt], b[cb][1]);
            }
        }
    };

    // ---- preamble ----
    ldA(0);
    cpB(0, 0);
    cpB(1, 1);
    stsA(0);
    ldA(1);
    cp_wait<1>();
    __syncthreads();
    ldA_frags(sb + aLane, 0, aF0);     // chunk 0, ks=0

#pragma unroll 1
    for (int kc = 0; kc < 16; ++kc) {
        const int abuf = kc & 1;
        if (kc + 2 < 16) cpB((kc + 2) % 3, kc + 2);

        const uint32_t aT2 = sb + abuf * ATILE + aLane;
        const uint32_t bT2 = sb + BOFF + (kc % 3) * BTILE + bLane;

        // ks=0: MMAs on aF0, preload aF1 (= this chunk's ks=1 fragments)
        phase(aF0, aF1, bT2, 0, aT2, 32, true);
        if (kc + 1 < 16) stsA(abuf ^ 1);     // STS next A chunk (overlaps MMA)
        if (kc + 2 < 16) ldA(kc + 2);        // LDG two chunks ahead
        // ks=1: MMAs on aF1, no preload (next chunk's buffer not published yet)
        phase(aF1, aF0, bT2, 32, 0, 0, false);

        if (kc + 2 < 16) cp_wait<1>(); else cp_wait<0>();
        __syncthreads();
        if (kc + 1 < 16)
            ldA_frags(sb + (abuf ^ 1) * ATILE + aLane, 0, aF0);  // next chunk ks=0
    }

    // ---- epilogue: s[m] += sum_n tanh(D + qeff[gid[m]][n]) * wv[n] ----
    const int n0 = wn * 64 + 2 * (lane & 3);
#pragma unroll
    for (int mt = 0; mt < 4; ++mt) {
#pragma unroll
        for (int h = 0; h < 2; ++h) {
            const int row = wm * 64 + mt * 16 + (lane >> 2) + h * 8;
            const int g = __ldg(gid + mBase + row);
            const float* qrow = qeff + (size_t)g * PD_ + nBase;
            float s = 0.f;
#pragma unroll
            for (int nt = 0; nt < 8; ++nt) {
                const int nn = n0 + nt * 8;
                float2 q2 = *reinterpret_cast<const float2*>(qrow + nn);
                float2 w2 = *reinterpret_cast<const float2*>(wv + nBase + nn);
                float x0 = tanhf(c[mt][nt][h * 2 + 0] + q2.x);
                float x1 = tanhf(c[mt][nt][h * 2 + 1] + q2.y);
                s = fmaf(x0, w2.x, s);
                s = fmaf(x1, w2.y, s);
            }
            s += __shfl_xor_sync(0xffffffffu, s, 1);
            s += __shfl_xor_sync(0xffffffffu, s, 2);
            if ((lane & 3) == 0) atomicAdd(&s_sm[row], s);
        }
    }
    __syncthreads();
    atomicAdd(&sOut[mBase + tid], s_sm[tid]);
}

// ---------------- prep kernels ----------------
__global__ void k_zero(float* sn, float* se, float* qn, float* qe) {
    int i = blockIdx.x * blockDim.x + threadIdx.x;
    if (i < TN_) sn[i] = 0.f;
    if (i < TE_) se[i] = 0.f;
    if (i < B_ * PD_) { qn[i] = 0.f; qe[i] = 0.f; }
}

// Wt[p][k] = bf16(W[k][p])  (512x512), grid.z selects node/edge
__global__ void k_transpose(const float* __restrict__ Wn, const float* __restrict__ We,
                            __nv_bfloat16* __restrict__ WtN, __nv_bfloat16* __restrict__ WtE) {
    const float* W = blockIdx.z ? We : Wn;
    __nv_bfloat16* Wt = blockIdx.z ? WtE : WtN;
    __shared__ float tile[32][33];
    int x = blockIdx.x * 32 + threadIdx.x;   // p
    int y = blockIdx.y * 32 + threadIdx.y;   // k
#pragma unroll
    for (int j = 0; j < 32; j += 8)
        tile[threadIdx.y + j][threadIdx.x] = W[(y + j) * 512 + x];
    __syncthreads();
    int xo = blockIdx.y * 32 + threadIdx.x;  // k
    int yo = blockIdx.x * 32 + threadIdx.y;  // p
#pragma unroll
    for (int j = 0; j < 32; j += 8)
        Wt[(yo + j) * 512 + xo] = __float2bfloat16(tile[threadIdx.x][threadIdx.y + j]);
}

// split-k qproj, grid (B_, 8, 2): z selects node/edge weights.
__global__ void __launch_bounds__(256) k_qproj(
    const float* __restrict__ q,
    const float* __restrict__ WqN, const float* __restrict__ bqN, const float* __restrict__ bhN,
    const float* __restrict__ WqE, const float* __restrict__ bqE, const float* __restrict__ bhE,
    float* __restrict__ outN, float* __restrict__ outE) {
    const float* Wq = blockIdx.z ? WqE : WqN;
    const float* bq = blockIdx.z ? bqE : bqN;
    const float* bh = blockIdx.z ? bhE : bhN;
    float* out = blockIdx.z ? outE : outN;
    __shared__ float qs[96];
    const int b = blockIdx.x, ks = blockIdx.y;
    const int k0 = ks * 96;
    const int t = threadIdx.x;
    if (t < 96) qs[t] = q[b * QD_ + k0 + t];
    __syncthreads();
    const int p0 = t, p1 = t + 256;
    float a0 = 0.f, a1 = 0.f;
#pragma unroll 4
    for (int k = 0; k < 96; ++k) {
        const float* wrow = Wq + (size_t)(k0 + k) * 512;
        a0 = fmaf(qs[k], __ldg(wrow + p0), a0);
        a1 = fmaf(qs[k], __ldg(wrow + p1), a1);
    }
    if (ks == 0) {
        a0 += __ldg(bq + p0) + __ldg(bh + p0);
        a1 += __ldg(bq + p1) + __ldg(bh + p1);
    }
    atomicAdd(out + b * 512 + p0, a0);
    atomicAdd(out + b * 512 + p1, a1);
}

// ---------------- fused per-graph softmax (gid sorted -> contiguous segments) ----
__global__ void __launch_bounds__(256) k_soft(
    const float* __restrict__ sn, const float* __restrict__ se,
    const int* __restrict__ gidN, const int* __restrict__ gidE,
    float* __restrict__ out) {
    const bool isNode = blockIdx.x < 64;
    const int g = isNode ? blockIdx.x : blockIdx.x - 64;
    const float* s  = isNode ? sn : se;
    const int* gid  = isNode ? gidN : gidE;
    const int n     = isNode ? TN_ : TE_;
    float* o        = out + (isNode ? 0 : TN_);

    const int t = threadIdx.x;
    __shared__ float red[256];
    __shared__ int bounds[2];

    if (t < 2) {
        int target = g + t;
        int lo = 0, hi = n;
        while (lo < hi) {
            int mid = (lo + hi) >> 1;
            if (__ldg(gid + mid) < target) lo = mid + 1; else hi = mid;
        }
        bounds[t] = lo;
    }
    __syncthreads();
    const int lo = bounds[0], hi = bounds[1];

    float m = -3.0e38f;
    for (int i = lo + t; i < hi; i += 256) m = fmaxf(m, __ldg(s + i));
    red[t] = m;
    __syncthreads();
#pragma unroll
    for (int st = 128; st >= 1; st >>= 1) {
        if (t < st) red[t] = fmaxf(red[t], red[t + st]);
        __syncthreads();
    }
    m = red[0];
    __syncthreads();

    float z = 0.f;
    for (int i = lo + t; i < hi; i += 256) z += expf(__ldg(s + i) - m);
    red[t] = z;
    __syncthreads();
#pragma unroll
    for (int st = 128; st >= 1; st >>= 1) {
        if (t < st) red[t] += red[t + st];
        __syncthreads();
    }
    const float rz = 1.f / red[0];

    for (int i = lo + t; i < hi; i += 256)
        o[i] = expf(__ldg(s + i) - m) * rz;
}

// ---------------- launch ----------------
extern "C" void kernel_launch(void* const* d_in, const int* in_sizes, int n_in,
                              void* d_out, int out_size) {
    const float* question = (const float*)d_in[0];
    const float* nodes    = (const float*)d_in[1];
    const float* edges    = (const float*)d_in[2];
    const float* W_nq     = (const float*)d_in[3];
    const float* b_nq     = (const float*)d_in[4];
    const float* W_n      = (const float*)d_in[5];
    const float* b_n      = (const float*)d_in[6];
    const float* w_nv     = (const float*)d_in[7];
    // d_in[8] = b_nv — softmax shift-invariant, unused
    const float* W_eq     = (const float*)d_in[9];
    const float* b_eq     = (const float*)d_in[10];
    const float* W_e      = (const float*)d_in[11];
    const float* b_e      = (const float*)d_in[12];
    const float* w_ev     = (const float*)d_in[13];
    // d_in[14] = b_ev — unused
    const int* node_gid   = (const int*)d_in[15];
    const int* edge_gid   = (const int*)d_in[16];
    float* out = (float*)d_out;

    float *qn, *qe, *sn, *se;
    __nv_bfloat16 *wtn, *wte;
    cudaGetSymbolAddress((void**)&qn,  g_qn);
    cudaGetSymbolAddress((void**)&qe,  g_qe);
    cudaGetSymbolAddress((void**)&wtn, g_wtn);
    cudaGetSymbolAddress((void**)&wte, g_wte);
    cudaGetSymbolAddress((void**)&sn,  g_sn);
    cudaGetSymbolAddress((void**)&se,  g_se);

    cudaFuncSetAttribute(k_main, cudaFuncAttributeMaxDynamicSharedMemorySize, SMEM_BYTES);

    k_zero<<<TE_ / 512, 512>>>(sn, se, qn, qe);
    k_transpose<<<dim3(16, 16, 2), dim3(32, 8)>>>(W_n, W_e, wtn, wte);
    k_qproj<<<dim3(B_, 8, 2), 256>>>(question,
                                     W_nq, b_nq, b_n,
                                     W_eq, b_eq, b_e, qn, qe);

    k_main<<<dim3(4, NYN + TE_ / 256), 256, SMEM_BYTES>>>(
        nodes, edges, node_gid, edge_gid, wtn, wte, qn, qe, w_nv, w_ev, sn, se);

    k_soft<<<128, 256>>>(sn, se, node_gid, edge_gid, out);
}

// round 10
// speedup vs baseline: 1.1565x; 1.0734x over previous
#include <cuda_runtime.h>
#include <cuda_bf16.h>
#include <cstdint>

#define DINLINE __device__ __forceinline__

// ---------------- problem sizes ----------------
#define B_  64
#define TN_ 131072
#define TE_ 262144
#define QD_ 768
#define PD_ 512
#define KD_ 512

// ---------------- device scratch ----------------
__device__ float g_qn[B_ * PD_];
__device__ float g_qe[B_ * PD_];
__device__ __nv_bfloat16 g_wtn[PD_ * KD_];   // W_n transposed [P][K], bf16
__device__ __nv_bfloat16 g_wte[PD_ * KD_];
__device__ float g_sn[TN_];
__device__ float g_se[TE_];

// ---------------- helpers ----------------
DINLINE void cp16(uint32_t s, const void* g) {
    asm volatile("cp.async.cg.shared.global [%0], [%1], 16;"
                 :: "r"(s), "l"(g) : "memory");
}
DINLINE void cp_commit() { asm volatile("cp.async.commit_group;" ::: "memory"); }
template<int N> DINLINE void cp_wait() {
    asm volatile("cp.async.wait_group %0;" :: "n"(N) : "memory");
}

DINLINE uint32_t smem_u32(const void* p) {
    uint32_t a;
    asm("{ .reg .u64 t; cvta.to.shared.u64 t, %1; cvt.u32.u64 %0, t; }"
        : "=r"(a) : "l"(p));
    return a;
}

DINLINE float tanh_fast(float x) {
    float y;
    asm("tanh.approx.f32 %0, %1;" : "=f"(y) : "f"(x));
    return y;
}

DINLINE void mma_bf16(float* c, const uint32_t* a, const uint32_t* b) {
    asm volatile(
        "mma.sync.aligned.m16n8k16.row.col.f32.bf16.bf16.f32 "
        "{%0,%1,%2,%3}, {%4,%5,%6,%7}, {%8,%9}, {%0,%1,%2,%3};"
        : "+f"(c[0]), "+f"(c[1]), "+f"(c[2]), "+f"(c[3])
        : "r"(a[0]), "r"(a[1]), "r"(a[2]), "r"(a[3]),
          "r"(b[0]), "r"(b[1]));
}

DINLINE void ldm_x4(uint32_t& r0, uint32_t& r1, uint32_t& r2, uint32_t& r3,
                    uint32_t addr) {
    asm volatile("ldmatrix.sync.aligned.m8n8.x4.shared.b16 {%0,%1,%2,%3}, [%4];"
                 : "=r"(r0), "=r"(r1), "=r"(r2), "=r"(r3) : "r"(addr));
}

DINLINE uint32_t pack_bf16x2(float lo, float hi) {
    __nv_bfloat162 v = __float22bfloat162_rn(make_float2(lo, hi));
    return *reinterpret_cast<uint32_t*>(&v);
}

// ---------------- main fused GEMM ----------------
// CTA: 256 threads (8 warps, 4 wm x 2 wn, warp tile 64x64).
// Tile: M=256, N=128 (blockIdx.x in 0..3), K=512 in 16 chunks of 32.
// blockIdx.y in [0,1536): y<512 -> nodes; else edges.
// SMEM (bf16, 80B padded rows):
//   A: 2 x (256 x 80B = 20480)  @ 0
//   B: 3 x (128 x 80B = 10240)  @ 40960
//   s_sm: 256 floats            @ 71680
#define ROWB   80u
#define ATILE  20480u
#define BTILE  10240u
#define BOFF   40960u
#define SM_OFF 71680u
#define SMEM_BYTES (71680 + 1024)
#define NYN 512              // node tiles in y

__global__ void __launch_bounds__(256, 1) k_main(
    const float* __restrict__ An, const float* __restrict__ Ae,
    const int* __restrict__ gidN, const int* __restrict__ gidE,
    const __nv_bfloat16* __restrict__ WtN, const __nv_bfloat16* __restrict__ WtE,
    const float* __restrict__ qN, const float* __restrict__ qE,
    const float* __restrict__ wvN, const float* __restrict__ wvE,
    float* __restrict__ sN, float* __restrict__ sE)
{
    extern __shared__ char smem[];
    float* s_sm = reinterpret_cast<float*>(smem + SM_OFF);

    const bool isNode = blockIdx.y < NYN;
    const int  ty     = isNode ? blockIdx.y : blockIdx.y - NYN;
    const float* __restrict__ A    = isNode ? An   : Ae;
    const int*   __restrict__ gid  = isNode ? gidN : gidE;
    const __nv_bfloat16* __restrict__ Wt = isNode ? WtN : WtE;
    const float* __restrict__ qeff = isNode ? qN   : qE;
    const float* __restrict__ wv   = isNode ? wvN  : wvE;
    float*       __restrict__ sOut = isNode ? sN   : sE;

    const int tid  = threadIdx.x;
    const int lane = tid & 31;
    const int warp = tid >> 5;
    const int wm   = warp & 3;   // M block of 64
    const int wn   = warp >> 2;  // N block of 64

    const int mBase = ty * 256;
    const int nBase = blockIdx.x * 128;

    const uint32_t sb = smem_u32(smem);

    s_sm[tid] = 0.f;

    // ---- A loader: 256 rows x 32 f32 per chunk; thread: 8 float4
    const int aRow = tid >> 3;
    const int aQ   = tid & 7;
    const float* Abase = A + (size_t)(mBase + aRow) * KD_ + aQ * 4;

    float4 ra[8];
    auto ldA = [&](int kc) {
        const float* p = Abase + kc * 32;
#pragma unroll
        for (int i = 0; i < 8; ++i)
            ra[i] = *reinterpret_cast<const float4*>(p + (size_t)i * 32 * KD_);
    };
    auto stsA = [&](int buf) {
        const uint32_t base = sb + buf * ATILE + aRow * ROWB + aQ * 8;
#pragma unroll
        for (int i = 0; i < 8; ++i) {
            uint32_t lo = pack_bf16x2(ra[i].x, ra[i].y);
            uint32_t hi = pack_bf16x2(ra[i].z, ra[i].w);
            asm volatile("st.shared.v2.b32 [%0], {%1,%2};"
                         :: "r"(base + i * 32 * ROWB), "r"(lo), "r"(hi) : "memory");
        }
    };
    // B: 128 n-rows x 32 bf16 per chunk = 8KB = 512 x 16B; thread does 2 cp16
    const int bIdx0 = tid * 2;
    auto cpB = [&](int slot, int kc) {
#pragma unroll
        for (int j = 0; j < 2; ++j) {
            int idx = bIdx0 + j;
            int n = idx >> 2, g = idx & 3;
            cp16(sb + BOFF + slot * BTILE + n * ROWB + g * 16,
                 Wt + (size_t)(nBase + n) * KD_ + kc * 32 + g * 8);
        }
        cp_commit();
    };

    float c[4][8][4];
#pragma unroll
    for (int mt = 0; mt < 4; ++mt)
#pragma unroll
        for (int nt = 0; nt < 8; ++nt)
#pragma unroll
            for (int i = 0; i < 4; ++i) c[mt][nt][i] = 0.f;

    // ---- ldmatrix per-lane offsets ----
    const int j = lane >> 3;
    const uint32_t aLane = (uint32_t)(wm * 64 + ((j & 1) << 3) + (lane & 7)) * ROWB
                         + (uint32_t)(j >> 1) * 16u;
    const uint32_t bLane = (uint32_t)(wn * 64 + ((j >> 1) << 3) + (lane & 7)) * ROWB
                         + (uint32_t)(j & 1) * 16u;

    // ---- register-resident A fragment sets (ping-pong, no copies) ----
    uint32_t aF0[4][4], aF1[4][4];

    auto ldA_frags = [&](uint32_t aT2, uint32_t ko, uint32_t (&a)[4][4]) {
#pragma unroll
        for (int mt = 0; mt < 4; ++mt)
            ldm_x4(a[mt][0], a[mt][1], a[mt][2], a[mt][3],
                   aT2 + mt * 16 * ROWB + ko);
    };

    // One MMA phase over 8 nt, B loaded in pairs and pipelined; optionally
    // preloads the next phase's A fragments under the last MMA group.
    auto phase = [&](const uint32_t (&aIn)[4][4], uint32_t (&aOut)[4][4],
                     uint32_t bT2, uint32_t ko,
                     uint32_t aT2n, uint32_t kon, bool preloadA) {
        uint32_t b[2][2][2];   // [buf][nt-in-pair][frag]
        ldm_x4(b[0][0][0], b[0][0][1], b[0][1][0], b[0][1][1], bT2 + ko);
#pragma unroll
        for (int p = 0; p < 4; ++p) {
            const int cb = p & 1, nb = cb ^ 1;
            if (p < 3) {
                ldm_x4(b[nb][0][0], b[nb][0][1], b[nb][1][0], b[nb][1][1],
                       bT2 + (uint32_t)(p + 1) * 16 * ROWB + ko);
            } else if (preloadA) {
                ldA_frags(aT2n, kon, aOut);
            }
#pragma unroll
            for (int mt = 0; mt < 4; ++mt) {
                mma_bf16(c[mt][2 * p],     aIn[mt], b[cb][0]);
                mma_bf16(c[mt][2 * p + 1], aIn[mt], b[cb][1]);
            }
        }
    };

    // ---- preamble ----
    ldA(0);
    cpB(0, 0);
    cpB(1, 1);
    stsA(0);
    ldA(1);
    cp_wait<1>();
    __syncthreads();
    ldA_frags(sb + aLane, 0, aF0);     // chunk 0, ks=0

#pragma unroll 1
    for (int kc = 0; kc < 16; ++kc) {
        const int abuf = kc & 1;
        if (kc + 2 < 16) cpB((kc + 2) % 3, kc + 2);

        const uint32_t aT2 = sb + abuf * ATILE + aLane;
        const uint32_t bT2 = sb + BOFF + (kc % 3) * BTILE + bLane;

        // ks=0: MMAs on aF0, preload aF1 (= this chunk's ks=1 fragments)
        phase(aF0, aF1, bT2, 0, aT2, 32, true);
        if (kc + 1 < 16) stsA(abuf ^ 1);     // STS next A chunk (overlaps MMA)
        if (kc + 2 < 16) ldA(kc + 2);        // LDG two chunks ahead
        // ks=1: MMAs on aF1, no preload (next chunk's buffer not published yet)
        phase(aF1, aF0, bT2, 32, 0, 0, false);

        if (kc + 2 < 16) cp_wait<1>(); else cp_wait<0>();
        __syncthreads();
        if (kc + 1 < 16)
            ldA_frags(sb + (abuf ^ 1) * ATILE + aLane, 0, aF0);  // next chunk ks=0
    }

    // ---- epilogue: s[m] += sum_n tanh(D + qeff[gid[m]][n]) * wv[n] ----
    const int n0 = wn * 64 + 2 * (lane & 3);
#pragma unroll
    for (int mt = 0; mt < 4; ++mt) {
#pragma unroll
        for (int h = 0; h < 2; ++h) {
            const int row = wm * 64 + mt * 16 + (lane >> 2) + h * 8;
            const int g = __ldg(gid + mBase + row);
            const float* qrow = qeff + (size_t)g * PD_ + nBase;
            float s = 0.f;
#pragma unroll
            for (int nt = 0; nt < 8; ++nt) {
                const int nn = n0 + nt * 8;
                float2 q2 = *reinterpret_cast<const float2*>(qrow + nn);
                float2 w2 = *reinterpret_cast<const float2*>(wv + nBase + nn);
                float x0 = tanh_fast(c[mt][nt][h * 2 + 0] + q2.x);
                float x1 = tanh_fast(c[mt][nt][h * 2 + 1] + q2.y);
                s = fmaf(x0, w2.x, s);
                s = fmaf(x1, w2.y, s);
            }
            s += __shfl_xor_sync(0xffffffffu, s, 1);
            s += __shfl_xor_sync(0xffffffffu, s, 2);
            if ((lane & 3) == 0) atomicAdd(&s_sm[row], s);
        }
    }
    __syncthreads();
    atomicAdd(&sOut[mBase + tid], s_sm[tid]);
}

// ---------------- prep kernels ----------------
__global__ void k_zero(float* sn, float* se, float* qn, float* qe) {
    int i = blockIdx.x * blockDim.x + threadIdx.x;
    if (i < TN_) sn[i] = 0.f;
    if (i < TE_) se[i] = 0.f;
    if (i < B_ * PD_) { qn[i] = 0.f; qe[i] = 0.f; }
}

// Wt[p][k] = bf16(W[k][p])  (512x512), grid.z selects node/edge
__global__ void k_transpose(const float* __restrict__ Wn, const float* __restrict__ We,
                            __nv_bfloat16* __restrict__ WtN, __nv_bfloat16* __restrict__ WtE) {
    const float* W = blockIdx.z ? We : Wn;
    __nv_bfloat16* Wt = blockIdx.z ? WtE : WtN;
    __shared__ float tile[32][33];
    int x = blockIdx.x * 32 + threadIdx.x;   // p
    int y = blockIdx.y * 32 + threadIdx.y;   // k
#pragma unroll
    for (int j = 0; j < 32; j += 8)
        tile[threadIdx.y + j][threadIdx.x] = W[(y + j) * 512 + x];
    __syncthreads();
    int xo = blockIdx.y * 32 + threadIdx.x;  // k
    int yo = blockIdx.x * 32 + threadIdx.y;  // p
#pragma unroll
    for (int j = 0; j < 32; j += 8)
        Wt[(yo + j) * 512 + xo] = __float2bfloat16(tile[threadIdx.x][threadIdx.y + j]);
}

// split-k qproj, grid (B_, 8, 2): z selects node/edge weights.
__global__ void __launch_bounds__(256) k_qproj(
    const float* __restrict__ q,
    const float* __restrict__ WqN, const float* __restrict__ bqN, const float* __restrict__ bhN,
    const float* __restrict__ WqE, const float* __restrict__ bqE, const float* __restrict__ bhE,
    float* __restrict__ outN, float* __restrict__ outE) {
    const float* Wq = blockIdx.z ? WqE : WqN;
    const float* bq = blockIdx.z ? bqE : bqN;
    const float* bh = blockIdx.z ? bhE : bhN;
    float* out = blockIdx.z ? outE : outN;
    __shared__ float qs[96];
    const int b = blockIdx.x, ks = blockIdx.y;
    const int k0 = ks * 96;
    const int t = threadIdx.x;
    if (t < 96) qs[t] = q[b * QD_ + k0 + t];
    __syncthreads();
    const int p0 = t, p1 = t + 256;
    float a0 = 0.f, a1 = 0.f;
#pragma unroll 4
    for (int k = 0; k < 96; ++k) {
        const float* wrow = Wq + (size_t)(k0 + k) * 512;
        a0 = fmaf(qs[k], __ldg(wrow + p0), a0);
        a1 = fmaf(qs[k], __ldg(wrow + p1), a1);
    }
    if (ks == 0) {
        a0 += __ldg(bq + p0) + __ldg(bh + p0);
        a1 += __ldg(bq + p1) + __ldg(bh + p1);
    }
    atomicAdd(out + b * 512 + p0, a0);
    atomicAdd(out + b * 512 + p1, a1);
}

// ---------------- fused per-graph softmax (gid sorted -> contiguous segments) ----
__global__ void __launch_bounds__(256) k_soft(
    const float* __restrict__ sn, const float* __restrict__ se,
    const int* __restrict__ gidN, const int* __restrict__ gidE,
    float* __restrict__ out) {
    const bool isNode = blockIdx.x < 64;
    const int g = isNode ? blockIdx.x : blockIdx.x - 64;
    const float* s  = isNode ? sn : se;
    const int* gid  = isNode ? gidN : gidE;
    const int n     = isNode ? TN_ : TE_;
    float* o        = out + (isNode ? 0 : TN_);

    const int t = threadIdx.x;
    __shared__ float red[256];
    __shared__ int bounds[2];

    if (t < 2) {
        int target = g + t;
        int lo = 0, hi = n;
        while (lo < hi) {
            int mid = (lo + hi) >> 1;
            if (__ldg(gid + mid) < target) lo = mid + 1; else hi = mid;
        }
        bounds[t] = lo;
    }
    __syncthreads();
    const int lo = bounds[0], hi = bounds[1];

    float m = -3.0e38f;
    for (int i = lo + t; i < hi; i += 256) m = fmaxf(m, __ldg(s + i));
    red[t] = m;
    __syncthreads();
#pragma unroll
    for (int st = 128; st >= 1; st >>= 1) {
        if (t < st) red[t] = fmaxf(red[t], red[t + st]);
        __syncthreads();
    }
    m = red[0];
    __syncthreads();

    float z = 0.f;
    for (int i = lo + t; i < hi; i += 256) z += __expf(__ldg(s + i) - m);
    red[t] = z;
    __syncthreads();
#pragma unroll
    for (int st = 128; st >= 1; st >>= 1) {
        if (t < st) red[t] += red[t + st];
        __syncthreads();
    }
    const float rz = 1.f / red[0];

    for (int i = lo + t; i < hi; i += 256)
        o[i] = __expf(__ldg(s + i) - m) * rz;
}

// ---------------- launch ----------------
extern "C" void kernel_launch(void* const* d_in, const int* in_sizes, int n_in,
                              void* d_out, int out_size) {
    const float* question = (const float*)d_in[0];
    const float* nodes    = (const float*)d_in[1];
    const float* edges    = (const float*)d_in[2];
    const float* W_nq     = (const float*)d_in[3];
    const float* b_nq     = (const float*)d_in[4];
    const float* W_n      = (const float*)d_in[5];
    const float* b_n      = (const float*)d_in[6];
    const float* w_nv     = (const float*)d_in[7];
    // d_in[8] = b_nv — softmax shift-invariant, unused
    const float* W_eq     = (const float*)d_in[9];
    const float* b_eq     = (const float*)d_in[10];
    const float* W_e      = (const float*)d_in[11];
    const float* b_e      = (const float*)d_in[12];
    const float* w_ev     = (const float*)d_in[13];
    // d_in[14] = b_ev — unused
    const int* node_gid   = (const int*)d_in[15];
    const int* edge_gid   = (const int*)d_in[16];
    float* out = (float*)d_out;

    float *qn, *qe, *sn, *se;
    __nv_bfloat16 *wtn, *wte;
    cudaGetSymbolAddress((void**)&qn,  g_qn);
    cudaGetSymbolAddress((void**)&qe,  g_qe);
    cudaGetSymbolAddress((void**)&wtn, g_wtn);
    cudaGetSymbolAddress((void**)&wte, g_wte);
    cudaGetSymbolAddress((void**)&sn,  g_sn);
    cudaGetSymbolAddress((void**)&se,  g_se);

    cudaFuncSetAttribute(k_main, cudaFuncAttributeMaxDynamicSharedMemorySize, SMEM_BYTES);

    k_zero<<<TE_ / 512, 512>>>(sn, se, qn, qe);
    k_transpose<<<dim3(16, 16, 2), dim3(32, 8)>>>(W_n, W_e, wtn, wte);
    k_qproj<<<dim3(B_, 8, 2), 256>>>(question,
                                     W_nq, b_nq, b_n,
                                     W_eq, b_eq, b_e, qn, qe);

    k_main<<<dim3(4, NYN + TE_ / 256), 256, SMEM_BYTES>>>(
        nodes, edges, node_gid, edge_gid, wtn, wte, qn, qe, w_nv, w_ev, sn, se);

    k_soft<<<128, 256>>>(sn, se, node_gid, edge_gid, out);
}